// round 12
// baseline (speedup 1.0000x reference)
#include <cuda_runtime.h>
#include <cuda_bf16.h>
#include <cstdint>

// LSTM (relu activations, forget_bias=1) + per-timestep dense.
// B=64, T=512, I=128, H=1024, O=128. Gate order in Wk columns: i, j, f, o.
//
// R11 = R10's two-half batch pipeline + R9's PROVEN acquire-polling barrier.
// Evidence: R8 (cg-poll) err 0.555, R10 (cg-poll) err 0.560, R7/R9
// (acquire-poll) err 3.2e-6 -> the relaxed-poll + trailing-acquire wait is
// the broken piece. Poll with ld.acquire.gpu every iteration instead.
//
// Two independent 32-row batch halves, separate partial buffers + split-phase
// barrier channels: each half's barrier waits and gate/update phase hide
// under the other half's MMA work (tensor pipe measured at mma.sync roofline).

#define Bsz   64
#define Tlen  512
#define Isz   128
#define Hsz   1024
#define KTOT  1152
#define G4    4096
#define Osz   128

#define NBLK  144        // 16 col-tiles x 9 K-splits, co-resident on 148 SMs
#define KSPL  9
#define CTILE 256        // z-columns per block
#define MHALF 32         // batch rows per half
#define KP    136        // padded k-stride (bf16) -> conflict-free ldmatrix
#define W_PLANE (CTILE * KP)    /* 34816 elems */
#define A_PLANE (MHALF * KP)    /*  4352 elems */
#define SMEM_BYTES ((2 * W_PLANE + 2 * A_PLANE) * 2)   /* 156672 B */

// ---- device-global scratch (allocation-free) ----
__device__ float          g_zpA[KSPL][MHALF * G4];            // half-A partials
__device__ float          g_zpB[KSPL][MHALF * G4];            // half-B partials
__device__ __nv_bfloat16  g_h_hi[Bsz * Hsz];
__device__ __nv_bfloat16  g_h_lo[Bsz * Hsz];
__device__ __nv_bfloat16  g_wT_hi[(size_t)G4 * KTOT];         // WkT[n][k] hi
__device__ __nv_bfloat16  g_wT_lo[(size_t)G4 * KTOT];         // WkT[n][k] lo
__device__ __nv_bfloat16  g_x_hi[Bsz * Tlen * Isz];
__device__ __nv_bfloat16  g_x_lo[Bsz * Tlen * Isz];
__device__ float          g_hout[(size_t)Bsz * Tlen * Hsz];   // 128 MB
__device__ unsigned       g_cA1, g_cA2, g_cB1, g_cB2;         // barrier channels

__device__ __forceinline__ float sigf(float x) { return 1.0f / (1.0f + __expf(-x)); }

// ---------------------------------------------------------------------------
// One-time preprocessing
// ---------------------------------------------------------------------------
__global__ void prep_w(const float* __restrict__ Wk) {
    __shared__ float tile[32][33];
    const int kb0 = blockIdx.x * 32;
    const int nb0 = blockIdx.y * 32;
    const int tx = threadIdx.x, ty = threadIdx.y;   // 32 x 8
    #pragma unroll
    for (int i = 0; i < 32; i += 8)
        tile[ty + i][tx] = Wk[(size_t)(kb0 + ty + i) * G4 + nb0 + tx];
    __syncthreads();
    #pragma unroll
    for (int i = 0; i < 32; i += 8) {
        int n = nb0 + ty + i, k = kb0 + tx;
        float v = tile[tx][ty + i];
        __nv_bfloat16 h = __float2bfloat16(v);
        size_t o = (size_t)n * KTOT + k;
        g_wT_hi[o] = h;
        g_wT_lo[o] = __float2bfloat16(v - __bfloat162float(h));
    }
}

__global__ void prep_x(const float* __restrict__ X) {
    int idx = blockIdx.x * 256 + threadIdx.x;
    float v = X[idx];
    __nv_bfloat16 h = __float2bfloat16(v);
    g_x_hi[idx] = h;
    g_x_lo[idx] = __float2bfloat16(v - __bfloat162float(h));
}

__global__ void init_state() {
    int idx = blockIdx.x * blockDim.x + threadIdx.x;
    if (idx < Bsz * Hsz) {
        g_h_hi[idx] = __float2bfloat16(0.0f);
        g_h_lo[idx] = __float2bfloat16(0.0f);
    }
    if (idx == 0) { g_cA1 = 0u; g_cA2 = 0u; g_cB1 = 0u; g_cB2 = 0u; }
}

__device__ __forceinline__ void mma16816(float* d, const uint32_t* a, const uint32_t* b) {
    asm volatile(
        "mma.sync.aligned.m16n8k16.row.col.f32.bf16.bf16.f32 "
        "{%0,%1,%2,%3}, {%4,%5,%6,%7}, {%8,%9}, {%0,%1,%2,%3};"
        : "+f"(d[0]), "+f"(d[1]), "+f"(d[2]), "+f"(d[3])
        : "r"(a[0]), "r"(a[1]), "r"(a[2]), "r"(a[3]), "r"(b[0]), "r"(b[1]));
}

__device__ __forceinline__ void ldsm4(uint32_t* r, uint32_t addr) {
    asm volatile("ldmatrix.sync.aligned.m8n8.x4.shared.b16 {%0,%1,%2,%3}, [%4];"
        : "=r"(r[0]), "=r"(r[1]), "=r"(r[2]), "=r"(r[3]) : "r"(addr));
}

// Split-phase grid barrier channel (flush-free: no membar.gl -> no CCTL.IVALL).
// arrive: block-wide completion (bar.sync) then one release-red.
// wait:   acquire-load polling (the PROVEN R7/R9 scheme), then bar.sync.
__device__ __forceinline__ void bar_arrive(unsigned* ctr) {
    __syncthreads();
    if (threadIdx.x == 0)
        asm volatile("red.release.gpu.add.u32 [%0], %1;" :: "l"(ctr), "r"(1u) : "memory");
}
__device__ __forceinline__ void bar_wait(unsigned* ctr, unsigned need) {
    if (threadIdx.x == 0) {
        unsigned v;
        do {
            asm volatile("ld.acquire.gpu.u32 %0, [%1];" : "=r"(v) : "l"(ctr) : "memory");
        } while (v < need);
    }
    __syncthreads();
}

// ---------------------------------------------------------------------------
// Persistent kernel: 144 blocks x 256 threads, 153 KB dynamic smem.
// Block (colb, ks): z-cols [colb*256,+256), K-slice [ks*128,+128) of 1152.
// Weight slice (hi+lo bf16) resident in smem for all 512 steps.
// Per step: GEMM(A) arrive(A1); GEMM(B) arrive(B1);
//           wait(A1) phaseB(A) arrive(A2); wait(B1) phaseB(B) arrive(B2).
// Next step's GEMM(X) gated on X2. Waits hide under the other half's MMA.
// ---------------------------------------------------------------------------
__global__ __launch_bounds__(256, 1) void lstm_persistent(const float* __restrict__ bias)
{
    extern __shared__ __align__(16) uint16_t sm[];
    uint16_t* __restrict__ w_sm = sm;                  // 2 planes [n][KP]
    uint16_t* __restrict__ a_sm = sm + 2 * W_PLANE;    // 2 planes [row][KP]

    const int bid  = blockIdx.x;
    const int colb = bid / KSPL;
    const int ks   = bid - colb * KSPL;
    const int cb   = colb * CTILE;
    const int kb   = ks * 128;          // within 1152 (ks=0 -> X slice)

    const int tid  = threadIdx.x;
    const int w    = tid >> 5;
    const int lane = tid & 31;
    const int gq   = lane >> 2;         // 0..7
    const int qq   = lane & 3;          // 0..3

    // ---- one-time: weight slice (hi+lo) -> smem ----
    {
        const uint4* __restrict__ whi = (const uint4*)g_wT_hi;   // [n][144] uint4
        const uint4* __restrict__ wlo = (const uint4*)g_wT_lo;
        #pragma unroll
        for (int i = 0; i < 32; ++i) {
            int idx   = i * 256 + tid;          // 0..8191
            int plane = idx >> 12;
            int rem   = idx & 4095;
            int n     = rem >> 4;
            int kq    = rem & 15;
            const uint4* src = plane ? wlo : whi;
            uint4 v = src[(size_t)(cb + n) * 144 + (kb >> 3) + kq];
            *(uint4*)&w_sm[plane * W_PLANE + n * KP + kq * 8] = v;
        }
    }

    // ---- per-lane ldmatrix base addresses ----
    const uint32_t sm_u32 = (uint32_t)__cvta_generic_to_shared(sm);
    const int g   = lane >> 3;
    const int rin = lane & 7;
    const uint32_t w_addr0 = sm_u32 +
        ((g >> 1) * W_PLANE + (w * 32 + rin) * KP + (g & 1) * 8) * 2;
    const uint32_t a_addr0 = sm_u32 +
        (2 * W_PLANE + ((g & 1) * 8 + rin) * KP + (g >> 1) * 8) * 2;

    // ---- Phase-B ownership: blocks 0..127, threads 0..127; per half:
    //      float2 index q = bid*128 + tid -> b_local = q>>9, n = (q&511)*2 ----
    const bool upd = (bid < 128) && (tid < 128);
    int b_local = 0, nb = 0;
    float2 creg[2] = {make_float2(0.f, 0.f), make_float2(0.f, 0.f)};
    float2 zb2[4];
    if (upd) {
        int q = bid * 128 + tid;
        b_local = q >> 9;
        nb = (q & 511) * 2;
        #pragma unroll
        for (int gg = 0; gg < 4; ++gg) {
            zb2[gg].x = bias[gg * Hsz + nb];
            zb2[gg].y = bias[gg * Hsz + nb + 1];
        }
        zb2[2].x += 1.0f;  zb2[2].y += 1.0f;   // TF forget_bias = 1
    }

    const uint4* __restrict__ xhi = (const uint4*)g_x_hi;   // [(b*T+t)][16]
    const uint4* __restrict__ xlo = (const uint4*)g_x_lo;
    const uint4* __restrict__ hhi = (const uint4*)g_h_hi;   // [b][128]
    const uint4* __restrict__ hlo = (const uint4*)g_h_lo;

    unsigned nA1 = 0, nA2 = 0, nB1 = 0, nB2 = 0;

    for (int t = 0; t < Tlen; ++t) {
        #pragma unroll
        for (int half = 0; half < 2; ++half) {
            // gate on h(t-1) of this half being complete (and zp consumed)
            bar_wait(half ? &g_cB2 : &g_cA2, half ? nB2 : nA2);

            // ---- stage A tile (32 rows x 128 k, hi+lo planes) ----
            #pragma unroll
            for (int i = 0; i < 4; ++i) {
                int idx   = i * 256 + tid;      // 0..1023
                int plane = idx >> 9;
                int rem   = idx & 511;
                int row   = rem >> 4;           // 0..31
                int kq    = rem & 15;
                int brow  = half * MHALF + row;
                uint4 v;
                if (ks == 0) {
                    const uint4* src = plane ? xlo : xhi;
                    v = src[((size_t)brow * Tlen + t) * 16 + kq];
                } else {
                    const uint4* src = plane ? hlo : hhi;
                    v = __ldcg(&src[(size_t)brow * 128 + ((kb - Isz) >> 3) + kq]);
                }
                *(uint4*)&a_sm[plane * A_PLANE + row * KP + kq * 8] = v;
            }
            __syncthreads();

            // ---- MMA: 32 x 256 x 128, 3 hi/lo terms, ldmatrix-fed ----
            float acc[2][4][4] = {};
            #pragma unroll
            for (int kk = 0; kk < 128; kk += 16) {
                uint32_t bh[4][2], bl[4][2];
                #pragma unroll
                for (int ni = 0; ni < 4; ++ni) {
                    uint32_t r[4];
                    ldsm4(r, w_addr0 + (ni * 8 * KP + kk) * 2);
                    bh[ni][0] = r[0];  bh[ni][1] = r[1];
                    bl[ni][0] = r[2];  bl[ni][1] = r[3];
                }
                #pragma unroll
                for (int mi = 0; mi < 2; ++mi) {
                    uint32_t ah[4], al[4];
                    ldsm4(ah, a_addr0 + (mi * 16 * KP + kk) * 2);
                    ldsm4(al, a_addr0 + A_PLANE * 2 + (mi * 16 * KP + kk) * 2);
                    #pragma unroll
                    for (int ni = 0; ni < 4; ++ni) {
                        mma16816(acc[mi][ni], ah, bh[ni]);   // hi*hi
                        mma16816(acc[mi][ni], ah, bl[ni]);   // hi*lo
                        mma16816(acc[mi][ni], al, bh[ni]);   // lo*hi
                    }
                }
            }

            // ---- write z partials for this half ----
            float* __restrict__ zp = half ? g_zpB[ks] : g_zpA[ks];
            #pragma unroll
            for (int mi = 0; mi < 2; ++mi)
                #pragma unroll
                for (int ni = 0; ni < 4; ++ni) {
                    int r   = mi * 16 + gq;
                    int col = cb + w * 32 + ni * 8 + qq * 2;
                    *(float2*)&zp[(size_t)r * G4 + col] =
                        make_float2(acc[mi][ni][0], acc[mi][ni][1]);
                    *(float2*)&zp[(size_t)(r + 8) * G4 + col] =
                        make_float2(acc[mi][ni][2], acc[mi][ni][3]);
                }

            bar_arrive(half ? &g_cB1 : &g_cA1);    // includes __syncthreads
            if (half) nB1 += NBLK; else nA1 += NBLK;
        }

        // ---- phase B for both halves (each wait hides under prior MMA) ----
        #pragma unroll
        for (int half = 0; half < 2; ++half) {
            bar_wait(half ? &g_cB1 : &g_cA1, half ? nB1 : nA1);

            if (upd) {
                const float* __restrict__ zpb =
                    half ? &g_zpB[0][0] : &g_zpA[0][0];
                const int zrow = b_local * G4 + nb;
                float2 z[4];
                #pragma unroll
                for (int gg = 0; gg < 4; ++gg) {
                    float2 v = zb2[gg];
                    #pragma unroll
                    for (int s = 0; s < KSPL; ++s) {
                        float2 p = __ldcg((const float2*)
                            &zpb[(size_t)s * (MHALF * G4) + zrow + gg * Hsz]);
                        v.x += p.x;  v.y += p.y;
                    }
                    z[gg] = v;
                }

                float2 hn;
                {
                    float ig = sigf(z[0].x);
                    float gg = fmaxf(z[1].x, 0.0f);   // relu cell-input
                    float fg = sigf(z[2].x);          // bias includes +1
                    float og = sigf(z[3].x);
                    float cn = fg * creg[half].x + ig * gg;
                    creg[half].x = cn;
                    hn.x = og * fmaxf(cn, 0.0f);      // relu output
                }
                {
                    float ig = sigf(z[0].y);
                    float gg = fmaxf(z[1].y, 0.0f);
                    float fg = sigf(z[2].y);
                    float og = sigf(z[3].y);
                    float cn = fg * creg[half].y + ig * gg;
                    creg[half].y = cn;
                    hn.y = og * fmaxf(cn, 0.0f);
                }

                int b = half * MHALF + b_local;
                __nv_bfloat16 hx = __float2bfloat16(hn.x);
                __nv_bfloat16 hy = __float2bfloat16(hn.y);
                __nv_bfloat162 hip; hip.x = hx; hip.y = hy;
                __nv_bfloat162 lop;
                lop.x = __float2bfloat16(hn.x - __bfloat162float(hx));
                lop.y = __float2bfloat16(hn.y - __bfloat162float(hy));
                int hw = (b * Hsz + nb) >> 1;
                ((uint32_t*)g_h_hi)[hw] = *(uint32_t*)&hip;
                ((uint32_t*)g_h_lo)[hw] = *(uint32_t*)&lop;
                *(float2*)&g_hout[((size_t)b * Tlen + t) * Hsz + nb] = hn;
            }

            bar_arrive(half ? &g_cB2 : &g_cA2);
            if (half) nB2 += NBLK; else nA2 += NBLK;
        }
    }
}

// ---------------------------------------------------------------------------
// Final dense: out[B*T][128] = g_hout @ Wd + bd.
// ---------------------------------------------------------------------------
#define KC 32
__global__ __launch_bounds__(256) void dense_kernel(
    const float* __restrict__ Wd, const float* __restrict__ bd,
    float* __restrict__ out)
{
    __shared__ float a_s[64][KC + 1];
    __shared__ float w_s[KC][128];

    const int rb  = blockIdx.y * 64;
    const int tid = threadIdx.x;
    const int ty  = tid >> 5;
    const int tx  = tid & 31;
    const int r0  = ty * 8;
    const int c0  = tx * 4;

    float acc[8][4] = {};

    for (int k0 = 0; k0 < Hsz; k0 += KC) {
        #pragma unroll
        for (int i = 0; i < 8; ++i)
            a_s[i * 8 + ty][tx] = g_hout[(size_t)(rb + i * 8 + ty) * Hsz + k0 + tx];
        #pragma unroll
        for (int i = 0; i < 16; ++i) {
            int k = i * 2 + (tid >> 7);
            int c = tid & 127;
            w_s[k][c] = Wd[(size_t)(k0 + k) * Osz + c];
        }
        __syncthreads();

        #pragma unroll
        for (int k = 0; k < KC; ++k) {
            float4 wv = *(const float4*)&w_s[k][c0];
            #pragma unroll
            for (int i = 0; i < 8; ++i) {
                float a = a_s[r0 + i][k];
                acc[i][0] += a * wv.x;  acc[i][1] += a * wv.y;
                acc[i][2] += a * wv.z;  acc[i][3] += a * wv.w;
            }
        }
        __syncthreads();
    }

    float4 bv = *(const float4*)&bd[c0];
    #pragma unroll
    for (int i = 0; i < 8; ++i) {
        float4 o;
        o.x = acc[i][0] + bv.x;  o.y = acc[i][1] + bv.y;
        o.z = acc[i][2] + bv.z;  o.w = acc[i][3] + bv.w;
        *(float4*)&out[(size_t)(rb + r0 + i) * Osz + c0] = o;
    }
}

extern "C" void kernel_launch(void* const* d_in, const int* in_sizes, int n_in,
                              void* d_out, int out_size)
{
    const float* X  = (const float*)d_in[0];   // [B, T, I]
    const float* Wk = (const float*)d_in[1];   // [I+H, 4H]
    const float* b  = (const float*)d_in[2];   // [4H]
    const float* Wd = (const float*)d_in[3];   // [H, O]
    const float* bd = (const float*)d_in[4];   // [O]
    float* out = (float*)d_out;                // [B, T, O]
    (void)in_sizes; (void)n_in; (void)out_size;

    cudaFuncSetAttribute(lstm_persistent,
                         cudaFuncAttributeMaxDynamicSharedMemorySize, SMEM_BYTES);

    prep_w<<<dim3(KTOT / 32, G4 / 32), dim3(32, 8)>>>(Wk);
    prep_x<<<(Bsz * Tlen * Isz) / 256, 256>>>(X);
    init_state<<<(Bsz * Hsz + 255) / 256, 256>>>();
    lstm_persistent<<<NBLK, 256, SMEM_BYTES>>>(b);
    dense_kernel<<<dim3(1, (Bsz * Tlen) / 64), 256>>>(Wd, bd, out);
}

// round 14
// speedup vs baseline: 1.0876x; 1.0876x over previous
#include <cuda_runtime.h>
#include <cuda_bf16.h>
#include <cstdint>

// LSTM (relu activations, forget_bias=1) + per-timestep dense.
// B=64, T=512, I=128, H=1024, O=128. Gate order in Wk columns: i, j, f, o.
//
// R13 = R12 with the staging bug fixed: R12's stage() loaded only 64 of the
// 128 k-columns per chunk (row=rem>>3, kq=rem&7 -> 8 uint4/row); the other
// half of the A tile was stale smem -> NaN. Now 8x256 cp.async ops stage the
// full 64x128 hi+lo tile (16 uint4/row), matching R11's proven indexing.
//
// Design (unchanged from R12):
//  - ONE grid barrier per step. Weight columns PERMUTED (newcol=unit*4+gate)
//    so each of 128 blocks owns all 4 gates of 8 hidden units over the FULL
//    K=1152: no K-split partials, block-local gate/c/h update (c in regs).
//  - h ping-pong buffered; the single barrier covers both h-visibility and
//    the read/write anti-dependency.
//  - Weight slice (hi+lo bf16, 145KB) persistent in smem; A chunks staged
//    with double-buffered cp.async.cg (L1-bypass -> coherent with ldcg world).
//  - Proven pieces: bf16 3-term hi/lo math, acquire-poll barrier, ldmatrix.

#define Bsz   64
#define Tlen  512
#define Isz   128
#define Hsz   1024
#define KTOT  1152
#define G4    4096
#define Osz   128

#define NBLK  128          // 4096 cols / 32 per block; co-resident on 148 SMs
#define CTILE 32           // z-cols per block = 8 units x 4 gates
#define NCHUNK 9           // K chunks of 128 (chunk 0 = X, 1..8 = h)
#define KPW   1160         // weight row stride (1152+8): conflict-free ldsm
#define KPA   136          // A row stride (128+8): conflict-free ldsm
#define WPLANE (CTILE * KPW)   /* 37120 elems */
#define APLANE (64 * KPA)      /*  8704 elems */
#define SMEM_BYTES ((2 * WPLANE + 4 * APLANE) * 2)   /* 218112 B */

// ---- device-global scratch (allocation-free) ----
__device__ __nv_bfloat16  g_h_hi[2][Bsz * Hsz];               // ping-pong h
__device__ __nv_bfloat16  g_h_lo[2][Bsz * Hsz];
__device__ __nv_bfloat16  g_wT_hi[(size_t)G4 * KTOT];         // WkT[newcol][k]
__device__ __nv_bfloat16  g_wT_lo[(size_t)G4 * KTOT];
__device__ __nv_bfloat16  g_x_hi[Bsz * Tlen * Isz];
__device__ __nv_bfloat16  g_x_lo[Bsz * Tlen * Isz];
__device__ float          g_hout[(size_t)Bsz * Tlen * Hsz];   // 128 MB
__device__ unsigned       g_bar;

__device__ __forceinline__ float sigf(float x) { return 1.0f / (1.0f + __expf(-x)); }

// ---------------------------------------------------------------------------
// One-time preprocessing. prep_w permutes columns: newcol = unit*4 + gate.
// ---------------------------------------------------------------------------
__global__ void prep_w(const float* __restrict__ Wk) {
    __shared__ float tile[32][33];
    const int kb0 = blockIdx.x * 32;
    const int nb0 = blockIdx.y * 32;
    const int tx = threadIdx.x, ty = threadIdx.y;   // 32 x 8
    #pragma unroll
    for (int i = 0; i < 32; i += 8)
        tile[ty + i][tx] = Wk[(size_t)(kb0 + ty + i) * G4 + nb0 + tx];
    __syncthreads();
    #pragma unroll
    for (int i = 0; i < 32; i += 8) {
        int n_orig = nb0 + ty + i;
        int k      = kb0 + tx;
        int unit   = n_orig & 1023;
        int gate   = n_orig >> 10;
        int newcol = unit * 4 + gate;
        float v = tile[tx][ty + i];
        __nv_bfloat16 h = __float2bfloat16(v);
        size_t o = (size_t)newcol * KTOT + k;
        g_wT_hi[o] = h;
        g_wT_lo[o] = __float2bfloat16(v - __bfloat162float(h));
    }
}

__global__ void prep_x(const float* __restrict__ X) {
    int idx = blockIdx.x * 256 + threadIdx.x;
    float v = X[idx];
    __nv_bfloat16 h = __float2bfloat16(v);
    g_x_hi[idx] = h;
    g_x_lo[idx] = __float2bfloat16(v - __bfloat162float(h));
}

__global__ void init_state() {
    int idx = blockIdx.x * blockDim.x + threadIdx.x;
    if (idx < Bsz * Hsz) {
        g_h_hi[0][idx] = __float2bfloat16(0.0f);   // phase 0 read at t=0
        g_h_lo[0][idx] = __float2bfloat16(0.0f);
    }
    if (idx == 0) g_bar = 0u;
}

// ---------------------------------------------------------------------------
__device__ __forceinline__ void mma16816(float* d, const uint32_t* a, const uint32_t* b) {
    asm volatile(
        "mma.sync.aligned.m16n8k16.row.col.f32.bf16.bf16.f32 "
        "{%0,%1,%2,%3}, {%4,%5,%6,%7}, {%8,%9}, {%0,%1,%2,%3};"
        : "+f"(d[0]), "+f"(d[1]), "+f"(d[2]), "+f"(d[3])
        : "r"(a[0]), "r"(a[1]), "r"(a[2]), "r"(a[3]), "r"(b[0]), "r"(b[1]));
}
__device__ __forceinline__ void ldsm4(uint32_t* r, uint32_t addr) {
    asm volatile("ldmatrix.sync.aligned.m8n8.x4.shared.b16 {%0,%1,%2,%3}, [%4];"
        : "=r"(r[0]), "=r"(r[1]), "=r"(r[2]), "=r"(r[3]) : "r"(addr));
}
__device__ __forceinline__ void cpa16(uint32_t dst, const void* src) {
    asm volatile("cp.async.cg.shared.global [%0], [%1], 16;" :: "r"(dst), "l"(src));
}
#define CPA_COMMIT() asm volatile("cp.async.commit_group;" ::: "memory")
#define CPA_WAIT(N)  asm volatile("cp.async.wait_group %0;" :: "n"(N) : "memory")

// Flush-free barrier, PROVEN acquire-polling wait (R7/R9/R11).
__device__ __forceinline__ void bar_arrive(unsigned* ctr) {
    __syncthreads();
    if (threadIdx.x == 0)
        asm volatile("red.release.gpu.add.u32 [%0], %1;" :: "l"(ctr), "r"(1u) : "memory");
}
__device__ __forceinline__ void bar_wait(unsigned* ctr, unsigned need) {
    if (threadIdx.x == 0) {
        unsigned v;
        do {
            asm volatile("ld.acquire.gpu.u32 %0, [%1];" : "=r"(v) : "l"(ctr) : "memory");
        } while (v < need);
    }
    __syncthreads();
}

// ---------------------------------------------------------------------------
// Persistent kernel: 128 blocks x 256 threads, 213 KB dynamic smem.
// Block bid: permuted z-cols [bid*32,+32) = units [bid*8,+8) x 4 gates, full K.
// ---------------------------------------------------------------------------
__global__ __launch_bounds__(256, 1) void lstm_persistent(const float* __restrict__ bias)
{
    extern __shared__ __align__(16) uint16_t sm[];
    uint16_t* __restrict__ w_sm = sm;                  // [plane][col][KPW]
    uint16_t* __restrict__ a_sm = sm + 2 * WPLANE;     // [buf][plane][row][KPA]
    float*    __restrict__ z_sm = (float*)a_sm;        // reused post-MMA: [64][36]

    const int bid  = blockIdx.x;
    const int cb   = bid * CTILE;      // permuted col base
    const int tid  = threadIdx.x;
    const int w    = tid >> 5;
    const int lane = tid & 31;
    const int gq   = lane >> 2;        // 0..7
    const int qq   = lane & 3;         // 0..3
    const int mi   = w & 3;            // m-tile (16 rows)
    const int nh   = w >> 2;           // n-half (16 cols)

    // ---- one-time: weight slice (32 cols x 1152 k, hi+lo) -> smem ----
    {
        const uint4* __restrict__ whi = (const uint4*)g_wT_hi;  // [col][144]
        const uint4* __restrict__ wlo = (const uint4*)g_wT_lo;
        for (int i = 0; i < 36; ++i) {
            int idx   = i * 256 + tid;           // 0..9215
            int plane = idx / 4608;
            int rem   = idx - plane * 4608;
            int col   = rem / 144;
            int kq    = rem - col * 144;
            const uint4* src = plane ? wlo : whi;
            uint4 v = src[(size_t)(cb + col) * 144 + kq];
            *(uint4*)&w_sm[plane * WPLANE + col * KPW + kq * 8] = v;
        }
    }

    // ---- ldmatrix base addresses ----
    const uint32_t sm_u32 = (uint32_t)__cvta_generic_to_shared(sm);
    const int g   = lane >> 3;
    const int rin = lane & 7;
    // W x4 = {hi k0-7, hi k8-15, lo k0-7, lo k8-15} for 8 cols (nh*16+ni*8+rin)
    const uint32_t w_addr0 = sm_u32 +
        ((g >> 1) * WPLANE + (nh * 16 + rin) * KPW + (g & 1) * 8) * 2;
    // A x4 = {a(r,k), a(r+8,k), a(r,k+8), a(r+8,k+8)}, rows mi*16+(g&1)*8+rin
    const uint32_t a_addr0 = sm_u32 +
        (2 * WPLANE + (mi * 16 + (g & 1) * 8 + rin) * KPA + (g >> 1) * 8) * 2;

    // ---- update-phase constants: thread owns (b, unit) pairs p=tid, tid+256
    //      p -> b = p>>3 (and +32), u = p&7; both pairs share u -> one bias ----
    const int uu = tid & 7;            // local unit 0..7
    const int b0 = tid >> 3;           // batch row for e=0 (e=1: +32)
    const int ug = cb / 4 + uu;        // global unit  (cb = unit0*4)
    float4 zb;
    zb.x = bias[ug];                   // i
    zb.y = bias[Hsz + ug];             // j
    zb.z = bias[2 * Hsz + ug] + 1.0f;  // f (+forget_bias)
    zb.w = bias[3 * Hsz + ug];         // o
    float creg[2] = {0.0f, 0.0f};

    const uint4* __restrict__ xhi = (const uint4*)g_x_hi;   // [(b*T+t)][16]
    const uint4* __restrict__ xlo = (const uint4*)g_x_lo;

    unsigned need = 0;

    for (int t = 0; t < Tlen; ++t) {
        const uint4* __restrict__ hhi = (const uint4*)g_h_hi[t & 1];  // [b][128]
        const uint4* __restrict__ hlo = (const uint4*)g_h_lo[t & 1];

        // ---- stage one 64x128 chunk (hi+lo planes) into buf via cp.async ----
        // FIXED vs R12: 8x256 = 2048 ops x 16B = full tile (16 uint4 per row).
        auto stage = [&](int c, int buf) {
            #pragma unroll
            for (int i = 0; i < 8; ++i) {
                int idx   = i * 256 + tid;        // 0..2047
                int plane = idx >> 10;
                int rem   = idx & 1023;
                int row   = rem >> 4;             // 0..63
                int kq    = rem & 15;             // 16 uint4 = 128 k
                const uint4* src;
                size_t off;
                if (c == 0) {
                    src = plane ? xlo : xhi;
                    off = ((size_t)row * Tlen + t) * 16 + kq;
                } else {
                    src = plane ? hlo : hhi;
                    off = (size_t)row * 128 + (c - 1) * 16 + kq;
                }
                uint32_t dst = sm_u32 +
                    (2 * WPLANE + ((buf * 2 + plane) * APLANE + row * KPA + kq * 8)) * 2;
                cpa16(dst, &src[off]);
            }
            CPA_COMMIT();
        };

        float acc[2][4] = {};   // 2 n-tiles x 4

        stage(0, 0);            // X chunk: independent of h
        bar_wait(&g_bar, need); // all blocks finished step t-1 (h phase t&1 final)
        stage(1, 1);

        #pragma unroll
        for (int c = 0; c < NCHUNK; ++c) {
            if (c == NCHUNK - 1) { CPA_WAIT(0); } else { CPA_WAIT(1); }
            __syncthreads();

            const int buf = c & 1;
            const uint32_t a_hi = a_addr0 + (buf * 2 * APLANE) * 2;
            const uint32_t a_lo = a_hi + APLANE * 2;
            const int kwoff = c * 128;

            #pragma unroll
            for (int kk = 0; kk < 128; kk += 16) {
                uint32_t bf[2][4];
                ldsm4(bf[0], w_addr0 + (kwoff + kk) * 2);
                ldsm4(bf[1], w_addr0 + (8 * KPW + kwoff + kk) * 2);
                uint32_t ah[4], al[4];
                ldsm4(ah, a_hi + kk * 2);
                ldsm4(al, a_lo + kk * 2);
                #pragma unroll
                for (int ni = 0; ni < 2; ++ni) {
                    mma16816(acc[ni], ah, &bf[ni][0]);   // hi*hi
                    mma16816(acc[ni], ah, &bf[ni][2]);   // hi*lo
                    mma16816(acc[ni], al, &bf[ni][0]);   // lo*hi
                }
            }
            __syncthreads();                 // done reading buf
            if (c + 2 < NCHUNK) stage(c + 2, buf);
        }

        // ---- z -> smem (reuse A region; all cp.async drained, bufs free) ----
        #pragma unroll
        for (int ni = 0; ni < 2; ++ni) {
            int row = mi * 16 + gq;
            int col = nh * 16 + ni * 8 + qq * 2;
            *(float2*)&z_sm[row * 36 + col]       = make_float2(acc[ni][0], acc[ni][1]);
            *(float2*)&z_sm[(row + 8) * 36 + col] = make_float2(acc[ni][2], acc[ni][3]);
        }
        __syncthreads();

        // ---- block-local gate/c/h update (512 (b,u) pairs, 2 per thread) ----
        __nv_bfloat16* __restrict__ hh = g_h_hi[(t + 1) & 1];
        __nv_bfloat16* __restrict__ hl = g_h_lo[(t + 1) & 1];
        #pragma unroll
        for (int e = 0; e < 2; ++e) {
            int b = b0 + e * 32;
            float4 zv = *(const float4*)&z_sm[b * 36 + 4 * uu];
            float ig = sigf(zv.x + zb.x);
            float gg = fmaxf(zv.y + zb.y, 0.0f);   // relu cell-input activation
            float fg = sigf(zv.z + zb.z);          // zb.z includes +1
            float og = sigf(zv.w + zb.w);
            float cn = fg * creg[e] + ig * gg;
            creg[e] = cn;
            float hn = og * fmaxf(cn, 0.0f);       // relu output activation

            __nv_bfloat16 hx = __float2bfloat16(hn);
            hh[b * Hsz + ug] = hx;
            hl[b * Hsz + ug] = __float2bfloat16(hn - __bfloat162float(hx));
            g_hout[((size_t)b * Tlen + t) * Hsz + ug] = hn;
        }

        bar_arrive(&g_bar);     // release orders the h stores above
        need += NBLK;
    }
}

// ---------------------------------------------------------------------------
// Final dense: out[B*T][128] = g_hout @ Wd + bd.
// ---------------------------------------------------------------------------
#define KC 32
__global__ __launch_bounds__(256) void dense_kernel(
    const float* __restrict__ Wd, const float* __restrict__ bd,
    float* __restrict__ out)
{
    __shared__ float a_s[64][KC + 1];
    __shared__ float w_s[KC][128];

    const int rb  = blockIdx.y * 64;
    const int tid = threadIdx.x;
    const int ty  = tid >> 5;
    const int tx  = tid & 31;
    const int r0  = ty * 8;
    const int c0  = tx * 4;

    float acc[8][4] = {};

    for (int k0 = 0; k0 < Hsz; k0 += KC) {
        #pragma unroll
        for (int i = 0; i < 8; ++i)
            a_s[i * 8 + ty][tx] = g_hout[(size_t)(rb + i * 8 + ty) * Hsz + k0 + tx];
        #pragma unroll
        for (int i = 0; i < 16; ++i) {
            int k = i * 2 + (tid >> 7);
            int c = tid & 127;
            w_s[k][c] = Wd[(size_t)(k0 + k) * Osz + c];
        }
        __syncthreads();

        #pragma unroll
        for (int k = 0; k < KC; ++k) {
            float4 wv = *(const float4*)&w_s[k][c0];
            #pragma unroll
            for (int i = 0; i < 8; ++i) {
                float a = a_s[r0 + i][k];
                acc[i][0] += a * wv.x;  acc[i][1] += a * wv.y;
                acc[i][2] += a * wv.z;  acc[i][3] += a * wv.w;
            }
        }
        __syncthreads();
    }

    float4 bv = *(const float4*)&bd[c0];
    #pragma unroll
    for (int i = 0; i < 8; ++i) {
        float4 o;
        o.x = acc[i][0] + bv.x;  o.y = acc[i][1] + bv.y;
        o.z = acc[i][2] + bv.z;  o.w = acc[i][3] + bv.w;
        *(float4*)&out[(size_t)(rb + r0 + i) * Osz + c0] = o;
    }
}

extern "C" void kernel_launch(void* const* d_in, const int* in_sizes, int n_in,
                              void* d_out, int out_size)
{
    const float* X  = (const float*)d_in[0];   // [B, T, I]
    const float* Wk = (const float*)d_in[1];   // [I+H, 4H]
    const float* b  = (const float*)d_in[2];   // [4H]
    const float* Wd = (const float*)d_in[3];   // [H, O]
    const float* bd = (const float*)d_in[4];   // [O]
    float* out = (float*)d_out;                // [B, T, O]
    (void)in_sizes; (void)n_in; (void)out_size;

    cudaFuncSetAttribute(lstm_persistent,
                         cudaFuncAttributeMaxDynamicSharedMemorySize, SMEM_BYTES);

    prep_w<<<dim3(KTOT / 32, G4 / 32), dim3(32, 8)>>>(Wk);
    prep_x<<<(Bsz * Tlen * Isz) / 256, 256>>>(X);
    init_state<<<(Bsz * Hsz + 255) / 256, 256>>>();
    lstm_persistent<<<NBLK, 256, SMEM_BYTES>>>(b);
    dense_kernel<<<dim3(1, (Bsz * Tlen) / 64), 256>>>(Wd, bd, out);
}

// round 16
// speedup vs baseline: 1.3561x; 1.2469x over previous
#include <cuda_runtime.h>
#include <cuda_fp16.h>
#include <cstdint>

// LSTM (relu activations, forget_bias=1) + per-timestep dense.
// B=64, T=512, I=128, H=1024, O=128. Gate order in Wk columns: i, j, f, o.
//
// R15 = R9's PROVEN skeleton with fp16 2-term math (a_fp16 x (w_hi + w_lo)).
// Justification: R8's fp16 failure is now attributed to the broken cg-poll
// barrier (R10 reproduced the same 0.55-class error with proven bf16 3-term
// math + cg-poll). With the acquire-poll barrier, fp16 2-term predicts
// rel_err ~1e-4 (R9 measured 3.2e-6 at 2^-16 h-storage; fp16 is 2^-11).
// Gains: MMA work -33% (measured at the mma.sync roofline), staging and
// h-state traffic -50%.
// NOTE (R14 lesson): harness targets sm_103 (no 'a') -> tcgen05 unavailable.

#define Bsz   64
#define Tlen  512
#define Isz   128
#define Hsz   1024
#define KTOT  1152
#define G4    4096
#define Osz   128

#define NBLK  144        // 16 col-tiles x 9 K-splits, co-resident on 148 SMs
#define KSPL  9
#define CTILE 256        // z-columns per block
#define KP    136        // padded k-stride (fp16) -> conflict-free ldmatrix
#define W_PLANE (CTILE * KP)   /* 34816 elems */
#define A_PLANE (64 * KP)      /*  8704 elems */
#define SMEM_BYTES ((2 * W_PLANE + A_PLANE) * 2)   /* 156672 B */

// ---- device-global scratch (allocation-free) ----
__device__ float     g_zp[KSPL][Bsz * G4];               // K-split partials
__device__ __half    g_h[Bsz * Hsz];                     // hidden state, fp16
__device__ __half    g_wT_hi[(size_t)G4 * KTOT];         // WkT[n][k] hi
__device__ __half    g_wT_lo[(size_t)G4 * KTOT];         // WkT[n][k] lo
__device__ __half    g_x[Bsz * Tlen * Isz];              // X, fp16
__device__ float     g_hout[(size_t)Bsz * Tlen * Hsz];   // 128 MB
__device__ unsigned  g_bar;

__device__ __forceinline__ float sigf(float x) { return 1.0f / (1.0f + __expf(-x)); }

// ---------------------------------------------------------------------------
// One-time preprocessing
// ---------------------------------------------------------------------------
__global__ void prep_w(const float* __restrict__ Wk) {
    __shared__ float tile[32][33];
    const int kb0 = blockIdx.x * 32;
    const int nb0 = blockIdx.y * 32;
    const int tx = threadIdx.x, ty = threadIdx.y;   // 32 x 8
    #pragma unroll
    for (int i = 0; i < 32; i += 8)
        tile[ty + i][tx] = Wk[(size_t)(kb0 + ty + i) * G4 + nb0 + tx];
    __syncthreads();
    #pragma unroll
    for (int i = 0; i < 32; i += 8) {
        int n = nb0 + ty + i, k = kb0 + tx;
        float v = tile[tx][ty + i];
        __half h = __float2half(v);
        size_t o = (size_t)n * KTOT + k;
        g_wT_hi[o] = h;
        g_wT_lo[o] = __float2half(v - __half2float(h));
    }
}

__global__ void prep_x(const float* __restrict__ X) {
    int idx = blockIdx.x * 256 + threadIdx.x;
    g_x[idx] = __float2half(X[idx]);
}

__global__ void init_state() {
    int idx = blockIdx.x * blockDim.x + threadIdx.x;
    if (idx < Bsz * Hsz) g_h[idx] = __float2half(0.0f);
    if (idx == 0) g_bar = 0u;
}

// ---------------------------------------------------------------------------
__device__ __forceinline__ void mma16816(float* d, const uint32_t* a, const uint32_t* b) {
    asm volatile(
        "mma.sync.aligned.m16n8k16.row.col.f32.f16.f16.f32 "
        "{%0,%1,%2,%3}, {%4,%5,%6,%7}, {%8,%9}, {%0,%1,%2,%3};"
        : "+f"(d[0]), "+f"(d[1]), "+f"(d[2]), "+f"(d[3])
        : "r"(a[0]), "r"(a[1]), "r"(a[2]), "r"(a[3]), "r"(b[0]), "r"(b[1]));
}

__device__ __forceinline__ void ldsm4(uint32_t* r, uint32_t addr) {
    asm volatile("ldmatrix.sync.aligned.m8n8.x4.shared.b16 {%0,%1,%2,%3}, [%4];"
        : "=r"(r[0]), "=r"(r[1]), "=r"(r[2]), "=r"(r[3]) : "r"(addr));
}

// Flush-free grid barrier, PROVEN acquire-polling wait (R7/R9/R11).
// No membar.gl -> no CCTL.IVALL; mutable cross-SM data read via __ldcg.
__device__ __forceinline__ void grid_sync(unsigned& target) {
    __syncthreads();
    target += NBLK;
    if (threadIdx.x == 0) {
        asm volatile("red.release.gpu.add.u32 [%0], %1;" :: "l"(&g_bar), "r"(1u) : "memory");
        unsigned v;
        do {
            asm volatile("ld.acquire.gpu.u32 %0, [%1];" : "=r"(v) : "l"(&g_bar) : "memory");
        } while (v < target);
    }
    __syncthreads();
}

// ---------------------------------------------------------------------------
// Persistent kernel: 144 blocks x 256 threads, 153 KB dynamic smem.
// Block (colb, ks): z-cols [colb*256,+256), K-slice [ks*128,+128) of 1152.
// Weight slice (hi+lo fp16) resident in smem for all 512 steps.
// ---------------------------------------------------------------------------
__global__ __launch_bounds__(256, 1) void lstm_persistent(const float* __restrict__ bias)
{
    extern __shared__ __align__(16) uint16_t sm[];
    uint16_t* __restrict__ w_sm = sm;                  // 2 planes [n][KP]
    uint16_t* __restrict__ a_sm = sm + 2 * W_PLANE;    // 1 plane  [row][KP]

    const int bid  = blockIdx.x;
    const int colb = bid / KSPL;
    const int ks   = bid - colb * KSPL;
    const int cb   = colb * CTILE;
    const int kb   = ks * 128;          // within 1152 (ks=0 -> X slice)

    const int tid  = threadIdx.x;
    const int w    = tid >> 5;
    const int lane = tid & 31;
    const int gq   = lane >> 2;         // 0..7
    const int qq   = lane & 3;          // 0..3

    // ---- one-time: weight slice (hi+lo fp16) -> smem ----
    {
        const uint4* __restrict__ whi = (const uint4*)g_wT_hi;   // [n][144] uint4
        const uint4* __restrict__ wlo = (const uint4*)g_wT_lo;
        #pragma unroll
        for (int i = 0; i < 32; ++i) {
            int idx   = i * 256 + tid;          // 0..8191
            int plane = idx >> 12;
            int rem   = idx & 4095;
            int n     = rem >> 4;
            int kq    = rem & 15;
            const uint4* src = plane ? wlo : whi;
            uint4 v = src[(size_t)(cb + n) * 144 + (kb >> 3) + kq];
            *(uint4*)&w_sm[plane * W_PLANE + n * KP + kq * 8] = v;
        }
    }

    // ---- per-lane ldmatrix base addresses (verbatim R9 geometry) ----
    const uint32_t sm_u32 = (uint32_t)__cvta_generic_to_shared(sm);
    const int g   = lane >> 3;
    const int rin = lane & 7;
    // W x4 = {bh[k], bh[k+8], bl[k], bl[k+8]} for cols (w*32 + ni*8 + rin)
    const uint32_t w_addr0 = sm_u32 +
        ((g >> 1) * W_PLANE + (w * 32 + rin) * KP + (g & 1) * 8) * 2;
    // A x4 = {a(r,k), a(r+8,k), a(r,k+8), a(r+8,k+8)}; rows mi*16+(g&1)*8+rin
    const uint32_t a_addr0 = sm_u32 +
        (2 * W_PLANE + ((g & 1) * 8 + rin) * KP + (g >> 1) * 8) * 2;

    // ---- Phase-B ownership: 128 blocks x 256 threads, 1 float2 each ----
    const bool upd = (bid < 128);
    int bb = 0, nb = 0;
    float2 creg = make_float2(0.f, 0.f);
    float2 zb2[4];
    if (upd) {
        int q = bid * 256 + tid;       // 0..32767
        bb = q >> 9;                   // batch row 0..63
        nb = (q & 511) * 2;            // n, n+1
        #pragma unroll
        for (int gg = 0; gg < 4; ++gg) {
            zb2[gg].x = bias[gg * Hsz + nb];
            zb2[gg].y = bias[gg * Hsz + nb + 1];
        }
        zb2[2].x += 1.0f;  zb2[2].y += 1.0f;   // TF forget_bias = 1
    }

    const uint4* __restrict__ xg = (const uint4*)g_x;    // [(b*T+t)][16]
    const uint4* __restrict__ hg = (const uint4*)g_h;    // [b][128]

    float* __restrict__ zp = g_zp[ks];
    unsigned bar_target = 0;

    for (int t = 0; t < Tlen; ++t) {
        // ---- stage A tile (64 rows x 128 k, single fp16 plane) ----
        #pragma unroll
        for (int i = 0; i < 4; ++i) {
            int idx = i * 256 + tid;            // 0..1023
            int row = idx >> 4;
            int kq  = idx & 15;
            uint4 v;
            if (ks == 0) v = xg[((size_t)row * Tlen + t) * 16 + kq];
            else         v = __ldcg(&hg[(size_t)row * 128 + ((kb - Isz) >> 3) + kq]);
            *(uint4*)&a_sm[row * KP + kq * 8] = v;
        }
        __syncthreads();

        // ---- MMA: 64 x 256 x 128, 2 terms (a*w_hi + a*w_lo), ldmatrix-fed ----
        float acc[4][4][4] = {};
        #pragma unroll
        for (int kk = 0; kk < 128; kk += 16) {
            uint32_t bf[4][4];                  // per ni: {bh0, bh1, bl0, bl1}
            #pragma unroll
            for (int ni = 0; ni < 4; ++ni)
                ldsm4(bf[ni], w_addr0 + (ni * 8 * KP + kk) * 2);
            #pragma unroll
            for (int mi = 0; mi < 4; ++mi) {
                uint32_t ah[4];
                ldsm4(ah, a_addr0 + (mi * 16 * KP + kk) * 2);
                #pragma unroll
                for (int ni = 0; ni < 4; ++ni) {
                    mma16816(acc[mi][ni], ah, &bf[ni][0]);   // a * w_hi
                    mma16816(acc[mi][ni], ah, &bf[ni][2]);   // a * w_lo
                }
            }
        }
        __syncthreads();   // a_sm safe to restage next step

        // ---- write z partials ----
        #pragma unroll
        for (int mi = 0; mi < 4; ++mi)
            #pragma unroll
            for (int ni = 0; ni < 4; ++ni) {
                int r   = mi * 16 + gq;
                int col = cb + w * 32 + ni * 8 + qq * 2;
                *(float2*)&zp[(size_t)r * G4 + col] =
                    make_float2(acc[mi][ni][0], acc[mi][ni][1]);
                *(float2*)&zp[(size_t)(r + 8) * G4 + col] =
                    make_float2(acc[mi][ni][2], acc[mi][ni][3]);
            }

        grid_sync(bar_target);   // partials visible

        // ---- Phase B: reduce partials -> gates -> c/h (1 float2/thread) ----
        if (upd) {
            const int zrow = bb * G4 + nb;
            float2 z[4];
            #pragma unroll
            for (int gg = 0; gg < 4; ++gg) {
                float2 v = zb2[gg];
                #pragma unroll
                for (int s = 0; s < KSPL; ++s) {
                    float2 p = __ldcg((const float2*)&g_zp[s][zrow + gg * Hsz]);
                    v.x += p.x;  v.y += p.y;
                }
                z[gg] = v;
            }

            float2 hn;
            {
                float ig = sigf(z[0].x);
                float gg = fmaxf(z[1].x, 0.0f);      // relu cell-input activation
                float fg = sigf(z[2].x);             // bias already includes +1
                float og = sigf(z[3].x);
                float cn = fg * creg.x + ig * gg;
                creg.x = cn;
                hn.x = og * fmaxf(cn, 0.0f);         // relu output activation
            }
            {
                float ig = sigf(z[0].y);
                float gg = fmaxf(z[1].y, 0.0f);
                float fg = sigf(z[2].y);
                float og = sigf(z[3].y);
                float cn = fg * creg.y + ig * gg;
                creg.y = cn;
                hn.y = og * fmaxf(cn, 0.0f);
            }

            // packed fp16 h store + fp32 history
            __half2 hp = __floats2half2_rn(hn.x, hn.y);
            ((uint32_t*)g_h)[(bb * Hsz + nb) >> 1] = *(uint32_t*)&hp;
            *(float2*)&g_hout[((size_t)bb * Tlen + t) * Hsz + nb] = hn;
        }

        grid_sync(bar_target);   // h visible before next step's staging
    }
}

// ---------------------------------------------------------------------------
// Final dense: out[B*T][128] = g_hout @ Wd + bd.  (verbatim R9)
// ---------------------------------------------------------------------------
#define KC 32
__global__ __launch_bounds__(256) void dense_kernel(
    const float* __restrict__ Wd, const float* __restrict__ bd,
    float* __restrict__ out)
{
    __shared__ float a_s[64][KC + 1];
    __shared__ float w_s[KC][128];

    const int rb  = blockIdx.y * 64;
    const int tid = threadIdx.x;
    const int ty  = tid >> 5;
    const int tx  = tid & 31;
    const int r0  = ty * 8;
    const int c0  = tx * 4;

    float acc[8][4] = {};

    for (int k0 = 0; k0 < Hsz; k0 += KC) {
        #pragma unroll
        for (int i = 0; i < 8; ++i)
            a_s[i * 8 + ty][tx] = g_hout[(size_t)(rb + i * 8 + ty) * Hsz + k0 + tx];
        #pragma unroll
        for (int i = 0; i < 16; ++i) {
            int k = i * 2 + (tid >> 7);
            int c = tid & 127;
            w_s[k][c] = Wd[(size_t)(k0 + k) * Osz + c];
        }
        __syncthreads();

        #pragma unroll
        for (int k = 0; k < KC; ++k) {
            float4 wv = *(const float4*)&w_s[k][c0];
            #pragma unroll
            for (int i = 0; i < 8; ++i) {
                float a = a_s[r0 + i][k];
                acc[i][0] += a * wv.x;  acc[i][1] += a * wv.y;
                acc[i][2] += a * wv.z;  acc[i][3] += a * wv.w;
            }
        }
        __syncthreads();
    }

    float4 bv = *(const float4*)&bd[c0];
    #pragma unroll
    for (int i = 0; i < 8; ++i) {
        float4 o;
        o.x = acc[i][0] + bv.x;  o.y = acc[i][1] + bv.y;
        o.z = acc[i][2] + bv.z;  o.w = acc[i][3] + bv.w;
        *(float4*)&out[(size_t)(rb + r0 + i) * Osz + c0] = o;
    }
}

extern "C" void kernel_launch(void* const* d_in, const int* in_sizes, int n_in,
                              void* d_out, int out_size)
{
    const float* X  = (const float*)d_in[0];   // [B, T, I]
    const float* Wk = (const float*)d_in[1];   // [I+H, 4H]
    const float* b  = (const float*)d_in[2];   // [4H]
    const float* Wd = (const float*)d_in[3];   // [H, O]
    const float* bd = (const float*)d_in[4];   // [O]
    float* out = (float*)d_out;                // [B, T, O]
    (void)in_sizes; (void)n_in; (void)out_size;

    cudaFuncSetAttribute(lstm_persistent,
                         cudaFuncAttributeMaxDynamicSharedMemorySize, SMEM_BYTES);

    prep_w<<<dim3(KTOT / 32, G4 / 32), dim3(32, 8)>>>(Wk);
    prep_x<<<(Bsz * Tlen * Isz) / 256, 256>>>(X);
    init_state<<<(Bsz * Hsz + 255) / 256, 256>>>();
    lstm_persistent<<<NBLK, 256, SMEM_BYTES>>>(b);
    dense_kernel<<<dim3(1, (Bsz * Tlen) / 64), 256>>>(Wd, bd, out);
}

// round 17
// speedup vs baseline: 1.4812x; 1.0922x over previous
#include <cuda_runtime.h>
#include <cuda_fp16.h>
#include <cstdint>

// LSTM (relu activations, forget_bias=1) + per-timestep dense.
// B=64, T=512, I=128, H=1024, O=128. Gate order in Wk columns: i, j, f, o.
//
// R16 = R13's ONE-barrier structure x R15's fp16 2-term arithmetic.
//  - Gate-permuted weights (newcol = unit*4 + gate): each of 128 blocks owns
//    all 4 gates of 8 hidden units over the FULL K=1152 -> no K-split
//    partials, no partial-exchange barrier, block-local c/h update.
//  - ONE grid barrier per step (R11 calibrated a barrier round at ~0.87us).
//  - fp16 2-term (a x (w_hi + w_lo)): cuts the R13 bottleneck (smem fragment
//    traffic) from 1.33MB to 885KB per block-step and halves A staging.
//  - h ping-pong fp16 planes; cp.async.cg double-buffered A chunks.
//  - PROVEN pieces: acquire-poll barrier (R7/R9/R11/R15), ldmatrix geometry,
//    R13 update layout (rel_err 7.8e-6 structural proof).
// NOTE (R14): harness targets sm_103 (no 'a') -> tcgen05 unavailable.

#define Bsz   64
#define Tlen  512
#define Isz   128
#define Hsz   1024
#define KTOT  1152
#define G4    4096
#define Osz   128

#define NBLK  128          // 4096 permuted cols / 32 per block
#define CTILE 32           // z-cols per block = 8 units x 4 gates
#define NCHUNK 9           // K chunks of 128 (chunk 0 = X, 1..8 = h)
#define KPW   1160         // weight row stride (1152+8): conflict-free ldsm
#define KPA   136          // A row stride (128+8): conflict-free ldsm
#define WPLANE (CTILE * KPW)   /* 37120 elems */
#define APLANE (64 * KPA)      /*  8704 elems */
#define SMEM_BYTES ((2 * WPLANE + 2 * APLANE) * 2)   /* 183296 B */

// ---- device-global scratch (allocation-free) ----
__device__ __half    g_h[2][Bsz * Hsz];                  // ping-pong h, fp16
__device__ __half    g_wT_hi[(size_t)G4 * KTOT];         // WkT[newcol][k] hi
__device__ __half    g_wT_lo[(size_t)G4 * KTOT];         // WkT[newcol][k] lo
__device__ __half    g_x[Bsz * Tlen * Isz];              // X, fp16
__device__ float     g_hout[(size_t)Bsz * Tlen * Hsz];   // 128 MB
__device__ unsigned  g_bar;

__device__ __forceinline__ float sigf(float x) { return 1.0f / (1.0f + __expf(-x)); }

// ---------------------------------------------------------------------------
// One-time preprocessing. prep_w permutes columns: newcol = unit*4 + gate.
// ---------------------------------------------------------------------------
__global__ void prep_w(const float* __restrict__ Wk) {
    __shared__ float tile[32][33];
    const int kb0 = blockIdx.x * 32;
    const int nb0 = blockIdx.y * 32;
    const int tx = threadIdx.x, ty = threadIdx.y;   // 32 x 8
    #pragma unroll
    for (int i = 0; i < 32; i += 8)
        tile[ty + i][tx] = Wk[(size_t)(kb0 + ty + i) * G4 + nb0 + tx];
    __syncthreads();
    #pragma unroll
    for (int i = 0; i < 32; i += 8) {
        int n_orig = nb0 + ty + i;
        int k      = kb0 + tx;
        int unit   = n_orig & 1023;
        int gate   = n_orig >> 10;
        int newcol = unit * 4 + gate;
        float v = tile[tx][ty + i];
        __half h = __float2half(v);
        size_t o = (size_t)newcol * KTOT + k;
        g_wT_hi[o] = h;
        g_wT_lo[o] = __float2half(v - __half2float(h));
    }
}

__global__ void prep_x(const float* __restrict__ X) {
    int idx = blockIdx.x * 256 + threadIdx.x;
    g_x[idx] = __float2half(X[idx]);
}

__global__ void init_state() {
    int idx = blockIdx.x * blockDim.x + threadIdx.x;
    if (idx < Bsz * Hsz) g_h[0][idx] = __float2half(0.0f);   // read at t=0
    if (idx == 0) g_bar = 0u;
}

// ---------------------------------------------------------------------------
__device__ __forceinline__ void mma16816(float* d, const uint32_t* a, const uint32_t* b) {
    asm volatile(
        "mma.sync.aligned.m16n8k16.row.col.f32.f16.f16.f32 "
        "{%0,%1,%2,%3}, {%4,%5,%6,%7}, {%8,%9}, {%0,%1,%2,%3};"
        : "+f"(d[0]), "+f"(d[1]), "+f"(d[2]), "+f"(d[3])
        : "r"(a[0]), "r"(a[1]), "r"(a[2]), "r"(a[3]), "r"(b[0]), "r"(b[1]));
}
__device__ __forceinline__ void ldsm4(uint32_t* r, uint32_t addr) {
    asm volatile("ldmatrix.sync.aligned.m8n8.x4.shared.b16 {%0,%1,%2,%3}, [%4];"
        : "=r"(r[0]), "=r"(r[1]), "=r"(r[2]), "=r"(r[3]) : "r"(addr));
}
__device__ __forceinline__ void cpa16(uint32_t dst, const void* src) {
    asm volatile("cp.async.cg.shared.global [%0], [%1], 16;" :: "r"(dst), "l"(src));
}
#define CPA_COMMIT() asm volatile("cp.async.commit_group;" ::: "memory")
#define CPA_WAIT1()  asm volatile("cp.async.wait_group 1;" ::: "memory")
#define CPA_WAIT0()  asm volatile("cp.async.wait_group 0;" ::: "memory")

// Flush-free grid barrier, PROVEN acquire-polling wait (R7/R9/R11/R15).
__device__ __forceinline__ void bar_arrive(unsigned* ctr) {
    __syncthreads();
    if (threadIdx.x == 0)
        asm volatile("red.release.gpu.add.u32 [%0], %1;" :: "l"(ctr), "r"(1u) : "memory");
}
__device__ __forceinline__ void bar_wait(unsigned* ctr, unsigned need) {
    if (threadIdx.x == 0) {
        unsigned v;
        do {
            asm volatile("ld.acquire.gpu.u32 %0, [%1];" : "=r"(v) : "l"(ctr) : "memory");
        } while (v < need);
    }
    __syncthreads();
}

// ---------------------------------------------------------------------------
// Persistent kernel: 128 blocks x 256 threads, 179 KB dynamic smem.
// Block bid: permuted z-cols [bid*32,+32) = units [bid*8,+8) x 4 gates, full K.
// ---------------------------------------------------------------------------
__global__ __launch_bounds__(256, 1) void lstm_persistent(const float* __restrict__ bias)
{
    extern __shared__ __align__(16) uint16_t sm[];
    uint16_t* __restrict__ w_sm = sm;                  // [plane][col][KPW]
    uint16_t* __restrict__ a_sm = sm + 2 * WPLANE;     // [buf][row][KPA]
    float*    __restrict__ z_sm = (float*)a_sm;        // reused post-MMA: [64][36]

    const int bid  = blockIdx.x;
    const int cb   = bid * CTILE;      // permuted col base
    const int tid  = threadIdx.x;
    const int w    = tid >> 5;
    const int lane = tid & 31;
    const int gq   = lane >> 2;        // 0..7
    const int qq   = lane & 3;         // 0..3
    const int mi   = w & 3;            // m-tile (16 rows)
    const int nh   = w >> 2;           // n-half (16 cols)

    // ---- one-time: weight slice (32 cols x 1152 k, hi+lo fp16) -> smem ----
    {
        const uint4* __restrict__ whi = (const uint4*)g_wT_hi;  // [col][144]
        const uint4* __restrict__ wlo = (const uint4*)g_wT_lo;
        for (int i = 0; i < 36; ++i) {
            int idx   = i * 256 + tid;           // 0..9215
            int plane = idx / 4608;
            int rem   = idx - plane * 4608;
            int col   = rem / 144;
            int kq    = rem - col * 144;
            const uint4* src = plane ? wlo : whi;
            uint4 v = src[(size_t)(cb + col) * 144 + kq];
            *(uint4*)&w_sm[plane * WPLANE + col * KPW + kq * 8] = v;
        }
    }

    // ---- ldmatrix base addresses (R13/R15 proven geometry) ----
    const uint32_t sm_u32 = (uint32_t)__cvta_generic_to_shared(sm);
    const int g   = lane >> 3;
    const int rin = lane & 7;
    // W x4 = {hi k0-7, hi k8-15, lo k0-7, lo k8-15} for cols nh*16 + ni*8 + rin
    const uint32_t w_addr0 = sm_u32 +
        ((g >> 1) * WPLANE + (nh * 16 + rin) * KPW + (g & 1) * 8) * 2;
    // A x4 = {a(r,k), a(r+8,k), a(r,k+8), a(r+8,k+8)}, rows mi*16+(g&1)*8+rin
    const uint32_t a_addr0 = sm_u32 +
        (2 * WPLANE + (mi * 16 + (g & 1) * 8 + rin) * KPA + (g >> 1) * 8) * 2;

    // ---- update constants: thread owns (b0, uu) and (b0+32, uu) ----
    const int uu = tid & 7;            // local unit 0..7
    const int b0 = tid >> 3;           // batch row for e=0 (e=1: +32)
    const int ug = cb / 4 + uu;        // global unit (cb = unit0*4)
    float4 zb;
    zb.x = bias[ug];                   // i
    zb.y = bias[Hsz + ug];             // j
    zb.z = bias[2 * Hsz + ug] + 1.0f;  // f (+forget_bias)
    zb.w = bias[3 * Hsz + ug];         // o
    float creg[2] = {0.0f, 0.0f};

    const uint4* __restrict__ xg = (const uint4*)g_x;   // [(b*T+t)][16]

    unsigned need = 0;

    for (int t = 0; t < Tlen; ++t) {
        const uint4* __restrict__ hg = (const uint4*)g_h[t & 1];   // [b][128]

        // ---- stage one 64x128 fp16 chunk into buf via cp.async ----
        auto stage = [&](int c, int buf) {
            #pragma unroll
            for (int i = 0; i < 4; ++i) {
                int idx = i * 256 + tid;          // 0..1023
                int row = idx >> 4;               // 0..63
                int kq  = idx & 15;               // 16 uint4 = 128 k
                const uint4* src;
                size_t off;
                if (c == 0) { src = xg; off = ((size_t)row * Tlen + t) * 16 + kq; }
                else        { src = hg; off = (size_t)row * 128 + (c - 1) * 16 + kq; }
                uint32_t dst = sm_u32 +
                    (2 * WPLANE + (buf * APLANE + row * KPA + kq * 8)) * 2;
                cpa16(dst, &src[off]);
            }
            CPA_COMMIT();
        };

        float acc[2][4] = {};   // 2 n-tiles x 4

        stage(0, 0);            // X chunk: independent of h
        bar_wait(&g_bar, need); // all blocks finished step t-1 (h[t&1] final)
        stage(1, 1);

        #pragma unroll
        for (int c = 0; c < NCHUNK; ++c) {
            if (c == NCHUNK - 1) { CPA_WAIT0(); } else { CPA_WAIT1(); }
            __syncthreads();

            const int buf = c & 1;
            const uint32_t a_base = a_addr0 + (buf * APLANE) * 2;
            const int kwoff = c * 128;

            #pragma unroll
            for (int kk = 0; kk < 128; kk += 16) {
                uint32_t bf[2][4];               // per ni: {bh0, bh1, bl0, bl1}
                ldsm4(bf[0], w_addr0 + (kwoff + kk) * 2);
                ldsm4(bf[1], w_addr0 + (8 * KPW + kwoff + kk) * 2);
                uint32_t ah[4];
                ldsm4(ah, a_base + kk * 2);
                #pragma unroll
                for (int ni = 0; ni < 2; ++ni) {
                    mma16816(acc[ni], ah, &bf[ni][0]);   // a * w_hi
                    mma16816(acc[ni], ah, &bf[ni][2]);   // a * w_lo
                }
            }
            __syncthreads();                 // done reading buf
            if (c + 2 < NCHUNK) stage(c + 2, buf);
        }

        // ---- z -> smem (reuse A region; all cp.async drained) ----
        #pragma unroll
        for (int ni = 0; ni < 2; ++ni) {
            int row = mi * 16 + gq;
            int col = nh * 16 + ni * 8 + qq * 2;
            *(float2*)&z_sm[row * 36 + col]       = make_float2(acc[ni][0], acc[ni][1]);
            *(float2*)&z_sm[(row + 8) * 36 + col] = make_float2(acc[ni][2], acc[ni][3]);
        }
        __syncthreads();

        // ---- block-local gate/c/h update (512 (b,u) pairs, 2 per thread) ----
        __half* __restrict__ hn_out = g_h[(t + 1) & 1];
        #pragma unroll
        for (int e = 0; e < 2; ++e) {
            int b = b0 + e * 32;
            float4 zv = *(const float4*)&z_sm[b * 36 + 4 * uu];
            float ig = sigf(zv.x + zb.x);
            float gg = fmaxf(zv.y + zb.y, 0.0f);   // relu cell-input activation
            float fg = sigf(zv.z + zb.z);          // zb.z includes +1
            float og = sigf(zv.w + zb.w);
            float cn = fg * creg[e] + ig * gg;
            creg[e] = cn;
            float hn = og * fmaxf(cn, 0.0f);       // relu output activation

            hn_out[b * Hsz + ug] = __float2half(hn);
            g_hout[((size_t)b * Tlen + t) * Hsz + ug] = hn;
        }

        bar_arrive(&g_bar);     // release orders the h stores above
        need += NBLK;
    }
}

// ---------------------------------------------------------------------------
// Final dense: out[B*T][128] = g_hout @ Wd + bd.  (verbatim R9/R15)
// ---------------------------------------------------------------------------
#define KC 32
__global__ __launch_bounds__(256) void dense_kernel(
    const float* __restrict__ Wd, const float* __restrict__ bd,
    float* __restrict__ out)
{
    __shared__ float a_s[64][KC + 1];
    __shared__ float w_s[KC][128];

    const int rb  = blockIdx.y * 64;
    const int tid = threadIdx.x;
    const int ty  = tid >> 5;
    const int tx  = tid & 31;
    const int r0  = ty * 8;
    const int c0  = tx * 4;

    float acc[8][4] = {};

    for (int k0 = 0; k0 < Hsz; k0 += KC) {
        #pragma unroll
        for (int i = 0; i < 8; ++i)
            a_s[i * 8 + ty][tx] = g_hout[(size_t)(rb + i * 8 + ty) * Hsz + k0 + tx];
        #pragma unroll
        for (int i = 0; i < 16; ++i) {
            int k = i * 2 + (tid >> 7);
            int c = tid & 127;
            w_s[k][c] = Wd[(size_t)(k0 + k) * Osz + c];
        }
        __syncthreads();

        #pragma unroll
        for (int k = 0; k < KC; ++k) {
            float4 wv = *(const float4*)&w_s[k][c0];
            #pragma unroll
            for (int i = 0; i < 8; ++i) {
                float a = a_s[r0 + i][k];
                acc[i][0] += a * wv.x;  acc[i][1] += a * wv.y;
                acc[i][2] += a * wv.z;  acc[i][3] += a * wv.w;
            }
        }
        __syncthreads();
    }

    float4 bv = *(const float4*)&bd[c0];
    #pragma unroll
    for (int i = 0; i < 8; ++i) {
        float4 o;
        o.x = acc[i][0] + bv.x;  o.y = acc[i][1] + bv.y;
        o.z = acc[i][2] + bv.z;  o.w = acc[i][3] + bv.w;
        *(float4*)&out[(size_t)(rb + r0 + i) * Osz + c0] = o;
    }
}

extern "C" void kernel_launch(void* const* d_in, const int* in_sizes, int n_in,
                              void* d_out, int out_size)
{
    const float* X  = (const float*)d_in[0];   // [B, T, I]
    const float* Wk = (const float*)d_in[1];   // [I+H, 4H]
    const float* b  = (const float*)d_in[2];   // [4H]
    const float* Wd = (const float*)d_in[3];   // [H, O]
    const float* bd = (const float*)d_in[4];   // [O]
    float* out = (float*)d_out;                // [B, T, O]
    (void)in_sizes; (void)n_in; (void)out_size;

    cudaFuncSetAttribute(lstm_persistent,
                         cudaFuncAttributeMaxDynamicSharedMemorySize, SMEM_BYTES);

    prep_w<<<dim3(KTOT / 32, G4 / 32), dim3(32, 8)>>>(Wk);
    prep_x<<<(Bsz * Tlen * Isz) / 256, 256>>>(X);
    init_state<<<(Bsz * Hsz + 255) / 256, 256>>>();
    lstm_persistent<<<NBLK, 256, SMEM_BYTES>>>(b);
    dense_kernel<<<dim3(1, (Bsz * Tlen) / 64), 256>>>(Wd, bd, out);
}